// round 13
// baseline (speedup 1.0000x reference)
#include <cuda_runtime.h>

#define L2E  1.4426950408889634f
#define LN2  0.6931471805599453f
#define BIGQ (-(1 << 27))

typedef unsigned long long u64;

__device__ __forceinline__ float ex2f_(float x){ float r; asm("ex2.approx.f32 %0, %1;" : "=f"(r) : "f"(x)); return r; }
__device__ __forceinline__ float lg2f_(float x){ float r; asm("lg2.approx.f32 %0, %1;" : "=f"(r) : "f"(x)); return r; }
__device__ __forceinline__ u64 pk2(float lo, float hi){ u64 r; asm("mov.b64 %0,{%1,%2};" : "=l"(r) : "f"(lo), "f"(hi)); return r; }
__device__ __forceinline__ void upk2(float& lo, float& hi, u64 v){ asm("mov.b64 {%0,%1},%2;" : "=f"(lo), "=f"(hi) : "l"(v)); }
__device__ __forceinline__ u64 fma2(u64 a, u64 b, u64 c){ u64 r; asm("fma.rn.f32x2 %0,%1,%2,%3;" : "=l"(r) : "l"(a), "l"(b), "l"(c)); return r; }

// exact e * 2^max(dq, -126), e in [1,2), dq <= 0  (pure ALU, no MUFU)
__device__ __forceinline__ float scl_(float e, int dq){
    int d = dq < -126 ? -126 : dq;
    return __uint_as_float(__float_as_uint(e) + ((unsigned)d << 23));
}

// One warp = TWO INDEPENDENT 2-pair anti-phase chains (same a, two b-pairs):
// 8 independent DP cell chains in flight per step -> in-warp ILP covers the
// ~45-cycle fixed-latency RAW chain that 1 warp/SMSP cannot otherwise hide.
// Weight-domain DP: w = e*2^q; softmin = exponent-aligned add (pure ALU);
// one ex2 per cell on the neighbor-independent distance term; per-chain
// SHFL pipelined one step ahead.
__global__ __launch_bounds__(128)
void sdtw_kernel(const float* __restrict__ X, const float* __restrict__ Y,
                 float* __restrict__ out)
{
    // 4 tiles; chain A = tiles 0..1, chain B = tiles 2..3 (B offset = 2*1152)
    // row j of tile t: sy[t*1152 + (j&3)*256 + c*128 + (j>>2)*4 + k]
    // nsqy = -L2E*|Y[j]|^2 at sy[t*1152 + 1024 + (j&3)*32 + (j>>2)]
    __shared__ __align__(16) float sy[4 * 1152];

    const int tid  = threadIdx.x;
    const int lane = tid & 31;
    const int wid  = tid >> 5;

    const int b0 = (blockIdx.x & 3) * 4;          // b-quad: A=(b0,b0+1), B=(b0+2,b0+3)
    const int a  = (blockIdx.x >> 2) * 4 + wid;

    for (int rep = 0; rep < 4; ++rep) {
        int gr   = tid + rep * 128;
        int tile = gr >> 7;
        int j    = gr & 127;
        const float* yrow = Y + (size_t)(b0 + tile) * 1024 + j * 8;
        float sq = 0.f;
        int base = tile * 1152 + (j & 3) * 256 + (j >> 2) * 4;
        #pragma unroll
        for (int k = 0; k < 8; ++k) {
            float vv = yrow[k];
            sq = fmaf(vv, vv, sq);
            sy[base + (k >> 2) * 128 + (k & 3)] = vv;
        }
        sy[tile * 1152 + 1024 + (j & 3) * 32 + (j >> 2)] = sq * (-L2E);
    }

    // X shared by both chains: xs2 = +2*L2E*x ; nsqx = -L2E*|x|^2
    u64   xs2[4][4];
    float nsqx[4];
    {
        const float* xp = X + (size_t)a * 1024 + lane * 32;
        #pragma unroll
        for (int s = 0; s < 4; ++s) {
            float acc = 0.f;
            #pragma unroll
            for (int kp = 0; kp < 4; ++kp) {
                float f0 = xp[s * 8 + 2 * kp];
                float f1 = xp[s * 8 + 2 * kp + 1];
                acc = fmaf(f0, f0, fmaf(f1, f1, acc));
                xs2[s][kp] = pk2(f0 * (2.0f * L2E), f1 * (2.0f * L2E));
            }
            nsqx[s] = acc * (-L2E);
        }
    }
    __syncthreads();

    // per-chain DP state + Y pipeline + shfl pipeline
    #define CH_DECL(C)                                                  \
        float e##C[2][4];  int q##C[2][4];                              \
        u64 yp##C[4][4];   float nyq##C[4];                             \
        float shCe##C = 1.0f, shPe##C = 1.0f;                           \
        int   shCq##C = BIGQ, shPq##C = BIGQ;
    CH_DECL(A)
    CH_DECL(B)
    #pragma unroll
    for (int s = 0; s < 4; ++s) {
        eA[0][s] = 1.0f; eA[1][s] = 1.0f; qA[0][s] = BIGQ; qA[1][s] = BIGQ;
        eB[0][s] = 1.0f; eB[1][s] = 1.0f; qB[0][s] = BIGQ; qB[1][s] = BIGQ;
    }
    #pragma unroll
    for (int b = 0; b < 4; ++b) {
        nyqA[b] = 0.f; nyqB[b] = 0.f;
        #pragma unroll
        for (int kp = 0; kp < 4; ++kp) { ypA[b][kp] = 0ull; ypB[b][kp] = 0ull; }
    }

    const int lane4 = lane * 4;

    // prologue: buffer 0 <- row ja0(p=0) = -lane4 (wrapped; real only for lane 0)
    {
        unsigned jb = (unsigned)(-lane4) & 255u;
        int t   = (int)(jb >> 7) * 1152;
        int off = (int)((jb >> 2) & 31u);
        int A0  = t + (int)(jb & 3u) * 256 + off * 4;
        float4 c0, c1;
        c0 = *reinterpret_cast<const float4*>(&sy[A0]);
        c1 = *reinterpret_cast<const float4*>(&sy[A0 + 128]);
        ypA[0][0] = pk2(c0.x, c0.y); ypA[0][1] = pk2(c0.z, c0.w);
        ypA[0][2] = pk2(c1.x, c1.y); ypA[0][3] = pk2(c1.z, c1.w);
        nyqA[0] = sy[t + 1024 + (int)(jb & 3u) * 32 + off];
        c0 = *reinterpret_cast<const float4*>(&sy[A0 + 2304]);
        c1 = *reinterpret_cast<const float4*>(&sy[A0 + 2304 + 128]);
        ypB[0][0] = pk2(c0.x, c0.y); ypB[0][1] = pk2(c0.z, c0.w);
        ypB[0][2] = pk2(c1.x, c1.y); ypB[0][3] = pk2(c1.z, c1.w);
        nyqB[0] = sy[t + 2304 + 1024 + (int)(jb & 3u) * 32 + off];
    }

    const int outA = a * 16 + b0;

    // one DP cell for chain C
    #define CELL(C, S, BUF, EU, QU, EL, QL, ED, QD, WI)                                \
    {                                                                                   \
        int qm = max(max((QU), (QL)), (QD));                                            \
        float sum = (scl_((EU), (QU) - qm) + scl_((EL), (QL) - qm))                     \
                  + scl_((ED), (QD) - qm);                                              \
        u64 acc2 = pk2(nsqx[S], nyq##C[BUF]);                                           \
        _Pragma("unroll")                                                               \
        for (int kp = 0; kp < 4; ++kp)                                                  \
            acc2 = fma2(xs2[S][kp], yp##C[BUF][kp], acc2);                              \
        float lo_, hi_; upk2(lo_, hi_, acc2);                                           \
        float w = sum * ex2f_(lo_ + hi_);                                               \
        unsigned wb = __float_as_uint(w);                                               \
        q##C[WI][S] = qm + (int)(wb >> 23) - 127;                                       \
        e##C[WI][S] = __uint_as_float((wb & 0x007FFFFFu) | 0x3F800000u);                \
    }

    // slot 3 of chain C (reads prev2 q[wIdx][2] before slot 2 overwrites it)
    #define SLOT3(C, U, WI, RI)                                                         \
    {                                                                                   \
        float el = e##C[RI][3], ed = e##C[WI][2];                                       \
        int ql, qd;                                                                     \
        if ((U) == 3) { ql = bj0 ? BIGQ : q##C[RI][3]; qd = bj0 ? BIGQ : q##C[WI][2]; } \
        else          { ql = q##C[RI][3];              qd = q##C[WI][2]; }              \
        CELL(C, 3, ((U) + 1) & 3, e##C[RI][2], q##C[RI][2], el, ql, ed, qd, WI)         \
    }

    #define SLOTM(C, S, U, WI, RI)                                                     \
    {                                                                                   \
        float el = e##C[RI][S], ed = e##C[WI][(S) - 1];                                 \
        int ql, qd;                                                                     \
        if ((S) == (U)) { ql = bj0 ? BIGQ : q##C[RI][S];                                \
                          qd = bj0 ? BIGQ : q##C[WI][(S) - 1]; }                        \
        else            { ql = q##C[RI][S]; qd = q##C[WI][(S) - 1]; }                   \
        CELL(C, S, ((U) - (S)) & 3, e##C[RI][(S) - 1], q##C[RI][(S) - 1],               \
             el, ql, ed, qd, WI)                                                        \
    }

    #define SLOT0(C, U, WI, RI)                                                        \
    {                                                                                   \
        float eu = shCe##C, el, ed;                                                     \
        int   qu = (lane == 0) ? BIGQ : shCq##C, ql, qd;                                \
        if ((U) == 0) {                                                                 \
            el = e##C[RI][0];  ql = bj0 ? BIGQ : q##C[RI][0];                           \
            if (lane == 0) { ed = 1.0f;      qd = bj0 ? 0 : BIGQ; }                     \
            else           { ed = shPe##C;   qd = bj0 ? BIGQ : shPq##C; }               \
        } else {                                                                        \
            el = e##C[RI][0];  ql = q##C[RI][0];                                        \
            ed = shPe##C;      qd = (lane == 0) ? BIGQ : shPq##C;                       \
        }                                                                               \
        CELL(C, 0, (U) & 3, eu, qu, el, ql, ed, qd, WI)                                 \
    }

    #define REFILL(C, OFFS)                                                             \
    {                                                                                   \
        const int Aa = ((u < 3) ? (baseY0 + (u + 1) * 256) : baseY1) + (OFFS);          \
        const int bb = (u + 1) & 3;                                                     \
        float4 c0 = *reinterpret_cast<const float4*>(&sy[Aa]);                          \
        float4 c1 = *reinterpret_cast<const float4*>(&sy[Aa + 128]);                    \
        yp##C[bb][0] = pk2(c0.x, c0.y); yp##C[bb][1] = pk2(c0.z, c0.w);                 \
        yp##C[bb][2] = pk2(c1.x, c1.y); yp##C[bb][3] = pk2(c1.z, c1.w);                 \
        nyq##C[bb] = (u < 3) ? sy[qb0 + (OFFS) + (u + 1) * 32] : sy[qb1 + (OFFS)];      \
    }

    for (int p0 = 0; p0 < 384; p0 += 4) {
        const int j0      = p0 - lane4;
        const unsigned jc = (unsigned)j0 & 255u;
        const unsigned jn = (unsigned)(j0 + 4) & 255u;
        const int tOff0   = (int)(jc >> 7) * 1152;
        const int m0      = (int)((jc >> 2) & 31u);
        const int baseY0  = tOff0 + m0 * 4;
        const int qb0     = tOff0 + 1024 + m0;
        const int tOff1   = (int)(jn >> 7) * 1152;
        const int m1      = (int)((jn >> 2) & 31u);
        const int baseY1  = tOff1 + m1 * 4;
        const int qb1     = tOff1 + 1024 + m1;
        const bool bj0    = ((jc & 127u) == 0u);   // same for both chains

        #pragma unroll
        for (int u = 0; u < 4; ++u) {
            const int wIdx = u & 1;
            const int rIdx = wIdx ^ 1;

            // slot 3 of both chains first, then their next-step shuffles
            SLOT3(A, u, wIdx, rIdx)
            SLOT3(B, u, wIdx, rIdx)

            const float shNeA = __shfl_up_sync(0xffffffffu, eA[wIdx][3], 1);
            const int   shNqA = __shfl_up_sync(0xffffffffu, qA[wIdx][3], 1);
            const float shNeB = __shfl_up_sync(0xffffffffu, eB[wIdx][3], 1);
            const int   shNqB = __shfl_up_sync(0xffffffffu, qB[wIdx][3], 1);

            REFILL(A, 0)
            REFILL(B, 2304)

            SLOTM(A, 2, u, wIdx, rIdx)
            SLOTM(B, 2, u, wIdx, rIdx)
            SLOTM(A, 1, u, wIdx, rIdx)
            SLOTM(B, 1, u, wIdx, rIdx)
            SLOT0(A, u, wIdx, rIdx)
            SLOT0(B, u, wIdx, rIdx)

            // harvest: pair0 at p=254 (p0=252,u=2), pair1 at p=382 (p0=380,u=2)
            if (u == 2 && lane == 31) {
                if (p0 == 252) {
                    out[outA]     = -((float)qA[0][3] + lg2f_(eA[0][3])) * LN2;
                    out[outA + 2] = -((float)qB[0][3] + lg2f_(eB[0][3])) * LN2;
                }
                if (p0 == 380) {
                    out[outA + 1] = -((float)qA[0][3] + lg2f_(eA[0][3])) * LN2;
                    out[outA + 3] = -((float)qB[0][3] + lg2f_(eB[0][3])) * LN2;
                }
            }

            // rotate shuffle pipelines
            shPeA = shCeA;  shPqA = shCqA;  shCeA = shNeA;  shCqA = shNqA;
            shPeB = shCeB;  shPqB = shCqB;  shCeB = shNeB;  shCqB = shNqB;
        }
    }
    #undef CELL
    #undef SLOT3
    #undef SLOTM
    #undef SLOT0
    #undef REFILL
    #undef CH_DECL
}

extern "C" void kernel_launch(void* const* d_in, const int* in_sizes, int n_in,
                              void* d_out, int out_size)
{
    const float* X = (const float*)d_in[0];
    const float* Y = (const float*)d_in[1];
    if (n_in >= 2 && in_sizes[0] < in_sizes[1]) {
        const float* t = X; X = Y; Y = t;
    }
    float* out = (float*)d_out;

    // 128 blocks x 128 threads: block = 4 a-values x one b-quad;
    // warp = two independent 2-pair chains (8 independent cell chains in flight).
    sdtw_kernel<<<128, 128>>>(X, Y, out);
}

// round 14
// speedup vs baseline: 1.1550x; 1.1550x over previous
#include <cuda_runtime.h>

#define L2E  1.4426950408889634f
#define LN2  0.6931471805599453f
#define BIGQ (-(1 << 27))

__device__ __forceinline__ float ex2f_(float x){ float r; asm("ex2.approx.f32 %0, %1;" : "=f"(r) : "f"(x)); return r; }
__device__ __forceinline__ float lg2f_(float x){ float r; asm("lg2.approx.f32 %0, %1;" : "=f"(r) : "f"(x)); return r; }

// exact e * 2^max(dq, -126), e in [1,2), dq <= 0  (pure ALU, no MUFU)
__device__ __forceinline__ float scl_(float e, int dq){
    int d = dq < -126 ? -126 : dq;
    return __uint_as_float(__float_as_uint(e) + ((unsigned)d << 23));
}

// One warp = FOUR (a,b) pairs chained in anti-phase (+128 steps each), 4 rows/thread,
// 1 warp per SMSP (128 blocks x 128 threads). Weight-domain DP: w = e*2^q;
// softmin = exponent-aligned add (pure ALU); one ex2 per cell on the
// neighbor-independent distance term; SHFL pipelined one step ahead.
// This round: SCALAR FFMA dot (no mov.b64 pack/unpack, no forced register pairs).
__global__ __launch_bounds__(128)
void sdtw_kernel(const float* __restrict__ X, const float* __restrict__ Y,
                 float* __restrict__ out)
{
    // 4 tiles; row j of tile t: sy[t*1152 + (j&3)*256 + c*128 + (j>>2)*4 + k]
    // nsqy = -L2E*|Y[j]|^2 at sy[t*1152 + 1024 + (j&3)*32 + (j>>2)]
    __shared__ __align__(16) float sy[4 * 1152];

    const int tid  = threadIdx.x;
    const int lane = tid & 31;
    const int wid  = tid >> 5;

    const int b0 = (blockIdx.x & 3) * 4;
    const int a  = (blockIdx.x >> 2) * 4 + wid;

    for (int rep = 0; rep < 4; ++rep) {
        int gr   = tid + rep * 128;
        int tile = gr >> 7;
        int j    = gr & 127;
        const float* yrow = Y + (size_t)(b0 + tile) * 1024 + j * 8;
        float sq = 0.f;
        int base = tile * 1152 + (j & 3) * 256 + (j >> 2) * 4;
        #pragma unroll
        for (int k = 0; k < 8; ++k) {
            float vv = yrow[k];
            sq = fmaf(vv, vv, sq);
            sy[base + (k >> 2) * 128 + (k & 3)] = vv;
        }
        sy[tile * 1152 + 1024 + (j & 3) * 32 + (j >> 2)] = sq * (-L2E);
    }

    // X: xs = +2*L2E*x ; nsqx = -L2E*|x|^2  ->  dot chain ends at -L2E*|x-y|^2
    float xs[4][8];
    float nsqx[4];
    {
        const float* xp = X + (size_t)a * 1024 + lane * 32;
        #pragma unroll
        for (int s = 0; s < 4; ++s) {
            float acc = 0.f;
            #pragma unroll
            for (int k = 0; k < 8; ++k) {
                float f = xp[s * 8 + k];
                acc = fmaf(f, f, acc);
                xs[s][k] = f * (2.0f * L2E);
            }
            nsqx[s] = acc * (-L2E);
        }
    }
    __syncthreads();

    // DP state: mantissa e in [1,2), exponent q (int). Masked == q very negative.
    float e[2][4];
    int   q[2][4];
    #pragma unroll
    for (int s = 0; s < 4; ++s) {
        e[0][s] = 1.0f; e[1][s] = 1.0f;
        q[0][s] = BIGQ; q[1][s] = BIGQ;
    }

    // Y register pipeline: buffer (p)&3 holds row ja0(p) = p - 4*lane, as plain floats.
    float yp[4][8];
    float nyq[4];
    #pragma unroll
    for (int b = 0; b < 4; ++b) {
        nyq[b] = 0.f;
        #pragma unroll
        for (int k = 0; k < 8; ++k) yp[b][k] = 0.f;
    }

    const int lane4 = lane * 4;

    // prologue: buffer 0 <- row ja0(p=0) = -lane4 (wrapped; real only for lane 0)
    {
        unsigned jb = (unsigned)(-lane4) & 511u;
        int t   = (int)(jb >> 7) * 1152;
        int off = (int)((jb >> 2) & 31u);
        int A   = t + (int)(jb & 3u) * 256 + off * 4;
        float4 c0 = *reinterpret_cast<const float4*>(&sy[A]);
        float4 c1 = *reinterpret_cast<const float4*>(&sy[A + 128]);
        yp[0][0] = c0.x; yp[0][1] = c0.y; yp[0][2] = c0.z; yp[0][3] = c0.w;
        yp[0][4] = c1.x; yp[0][5] = c1.y; yp[0][6] = c1.z; yp[0][7] = c1.w;
        nyq[0] = sy[t + 1024 + (int)(jb & 3u) * 32 + off];
    }

    // shuffle pipeline: shC = shfl of slot3 from step p-1 (this step's s=0 "up"),
    //                   shP = shfl of slot3 from step p-2 (this step's s=0 "diag").
    float shCe = 1.0f, shPe = 1.0f;
    int   shCq = BIGQ, shPq = BIGQ;

    const int outA = a * 16 + b0;

    // one DP cell: softmin(aligned add) * ex2(distance), exact exponent split
    #define CELL(S, BUF, EU, QU, EL, QL, ED, QD, WI)                                   \
    {                                                                                   \
        int qm = max(max((QU), (QL)), (QD));                                            \
        float sum = (scl_((EU), (QU) - qm) + scl_((EL), (QL) - qm))                     \
                  + scl_((ED), (QD) - qm);                                              \
        float acc = nsqx[S] + nyq[BUF];                                                 \
        _Pragma("unroll")                                                               \
        for (int k = 0; k < 8; ++k)                                                     \
            acc = fmaf(xs[S][k], yp[BUF][k], acc);                                      \
        float w = sum * ex2f_(acc);                                                     \
        unsigned wb = __float_as_uint(w);                                               \
        q[WI][S] = qm + (int)(wb >> 23) - 127;                                          \
        e[WI][S] = __uint_as_float((wb & 0x007FFFFFu) | 0x3F800000u);                   \
    }

    for (int p0 = 0; p0 < 640; p0 += 4) {
        const int j0      = p0 - lane4;
        const unsigned jc = (unsigned)j0 & 511u;
        const unsigned jn = (unsigned)(j0 + 4) & 511u;
        const int tOff0   = (int)(jc >> 7) * 1152;
        const int m0      = (int)((jc >> 2) & 31u);
        const int baseY0  = tOff0 + m0 * 4;
        const int qb0     = tOff0 + 1024 + m0;
        const int tOff1   = (int)(jn >> 7) * 1152;
        const int m1      = (int)((jn >> 2) & 31u);
        const int baseY1  = tOff1 + m1 * 4;
        const int qb1     = tOff1 + 1024 + m1;
        const bool bj0    = ((jc & 127u) == 0u);   // per-pair j==0 boundary: fires only at s==u
        const bool harv   = ((p0 & 127) == 124) && (p0 >= 252);

        #pragma unroll
        for (int u = 0; u < 4; ++u) {
            const int wIdx = u & 1;
            const int rIdx = wIdx ^ 1;

            // ---- slot 3 FIRST (reads prev2 q[wIdx][2] before slot 2 overwrites it) ----
            {
                float el = e[rIdx][3], ed = e[wIdx][2];
                int   ql, qd;
                if (u == 3) { ql = bj0 ? BIGQ : q[rIdx][3];  qd = bj0 ? BIGQ : q[wIdx][2]; }
                else        { ql = q[rIdx][3];               qd = q[wIdx][2]; }
                CELL(3, (u + 1) & 3, e[rIdx][2], q[rIdx][2], el, ql, ed, qd, wIdx)
            }

            // ---- shuffle slot3 for NEXT step, issued ~100 instr before its consumer ----
            const float shNe = __shfl_up_sync(0xffffffffu, e[wIdx][3], 1);
            const int   shNq = __shfl_up_sync(0xffffffffu, q[wIdx][3], 1);

            // ---- refill buffer (u+1)&3 (slot 3, its only pending reader, is done) ----
            {
                const int A = (u < 3) ? (baseY0 + (u + 1) * 256) : baseY1;
                const int b = (u + 1) & 3;
                float4 c0 = *reinterpret_cast<const float4*>(&sy[A]);
                float4 c1 = *reinterpret_cast<const float4*>(&sy[A + 128]);
                yp[b][0] = c0.x; yp[b][1] = c0.y; yp[b][2] = c0.z; yp[b][3] = c0.w;
                yp[b][4] = c1.x; yp[b][5] = c1.y; yp[b][6] = c1.z; yp[b][7] = c1.w;
                nyq[b] = (u < 3) ? sy[qb0 + (u + 1) * 32] : sy[qb1];
            }

            // ---- slots 2, 1 ----
            #pragma unroll
            for (int s = 2; s >= 1; --s) {
                float el = e[rIdx][s], ed = e[wIdx][s - 1];
                int   ql, qd;
                if (s == u) { ql = bj0 ? BIGQ : q[rIdx][s];  qd = bj0 ? BIGQ : q[wIdx][s - 1]; }
                else        { ql = q[rIdx][s];               qd = q[wIdx][s - 1]; }
                CELL(s, (u - s) & 3, e[rIdx][s - 1], q[rIdx][s - 1], el, ql, ed, qd, wIdx)
            }

            // ---- slot 0 (consumes the shuffles issued LAST step: shC/shP) ----
            {
                float eu = shCe, el, ed;
                int   qu = (lane == 0) ? BIGQ : shCq, ql, qd;
                if (u == 0) {
                    el = e[rIdx][0];  ql = bj0 ? BIGQ : q[rIdx][0];
                    if (lane == 0) { ed = 1.0f;  qd = bj0 ? 0 : BIGQ; }   // corner seed of each pair
                    else           { ed = shPe;  qd = bj0 ? BIGQ : shPq; }
                } else {
                    el = e[rIdx][0];  ql = q[rIdx][0];
                    ed = shPe;        qd = (lane == 0) ? BIGQ : shPq;
                }
                CELL(0, u & 3, eu, qu, el, ql, ed, qd, wIdx)
            }

            // harvest pair k at p = 128k + 254 (u == 2 within its block)
            if (u == 2 && harv && lane == 31) {
                int k = (p0 - 252) >> 7;
                out[outA + k] = -((float)q[0][3] + lg2f_(e[0][3])) * LN2;
            }

            // rotate shuffle pipeline
            shPe = shCe;  shPq = shCq;
            shCe = shNe;  shCq = shNq;
        }
    }
    #undef CELL
}

extern "C" void kernel_launch(void* const* d_in, const int* in_sizes, int n_in,
                              void* d_out, int out_size)
{
    const float* X = (const float*)d_in[0];
    const float* Y = (const float*)d_in[1];
    if (n_in >= 2 && in_sizes[0] < in_sizes[1]) {
        const float* t = X; X = Y; Y = t;
    }
    float* out = (float*)d_out;

    // 128 blocks x 128 threads: block = 4 a-values x one b-quad; warp = 4 chained pairs.
    // <=1 block per SM -> exactly 1 warp per SMSP, uniform load.
    sdtw_kernel<<<128, 128>>>(X, Y, out);
}

// round 15
// speedup vs baseline: 1.1926x; 1.0325x over previous
#include <cuda_runtime.h>

#define L2E  1.4426950408889634f
#define LN2  0.6931471805599453f
#define BIGQ (-(1 << 27))

__device__ __forceinline__ float ex2f_(float x){ float r; asm("ex2.approx.f32 %0, %1;" : "=f"(r) : "f"(x)); return r; }
__device__ __forceinline__ float lg2f_(float x){ float r; asm("lg2.approx.f32 %0, %1;" : "=f"(r) : "f"(x)); return r; }

// exact e * 2^max(dq, -126), e in [1,2), dq <= 0.
// shift-add written as bits + d*2^23 -> single IMAD (fma pipe), clamp+sub on alu.
__device__ __forceinline__ float scl_(float e, int dq){
    int d = dq < -126 ? -126 : dq;
    return __uint_as_float(__float_as_uint(e) + (unsigned)d * 8388608u);
}

// One warp = FOUR (a,b) pairs chained in anti-phase (+128 steps each), 4 rows/thread,
// 1 warp per SMSP (128 blocks x 128 threads). Weight-domain DP: w = e*2^q;
// softmin = exponent-aligned add (pure ALU); one ex2 per cell (neighbor-independent);
// SHFL pipelined one step ahead; scalar FFMA dot. This round: branch-free harvest
// (no BSSY/BSYNC divergence machinery in the hot loop) + IMAD/IADD3 micro-forms.
__global__ __launch_bounds__(128, 1)
void sdtw_kernel(const float* __restrict__ X, const float* __restrict__ Y,
                 float* __restrict__ out)
{
    // 4 tiles; row j of tile t: sy[t*1152 + (j&3)*256 + c*128 + (j>>2)*4 + k]
    // nsqy = -L2E*|Y[j]|^2 at sy[t*1152 + 1024 + (j&3)*32 + (j>>2)]
    __shared__ __align__(16) float sy[4 * 1152];

    const int tid  = threadIdx.x;
    const int lane = tid & 31;
    const int wid  = tid >> 5;

    const int b0 = (blockIdx.x & 3) * 4;
    const int a  = (blockIdx.x >> 2) * 4 + wid;

    for (int rep = 0; rep < 4; ++rep) {
        int gr   = tid + rep * 128;
        int tile = gr >> 7;
        int j    = gr & 127;
        const float* yrow = Y + (size_t)(b0 + tile) * 1024 + j * 8;
        float sq = 0.f;
        int base = tile * 1152 + (j & 3) * 256 + (j >> 2) * 4;
        #pragma unroll
        for (int k = 0; k < 8; ++k) {
            float vv = yrow[k];
            sq = fmaf(vv, vv, sq);
            sy[base + (k >> 2) * 128 + (k & 3)] = vv;
        }
        sy[tile * 1152 + 1024 + (j & 3) * 32 + (j >> 2)] = sq * (-L2E);
    }

    // X: xs = +2*L2E*x ; nsqx = -L2E*|x|^2  ->  dot chain ends at -L2E*|x-y|^2
    float xs[4][8];
    float nsqx[4];
    {
        const float* xp = X + (size_t)a * 1024 + lane * 32;
        #pragma unroll
        for (int s = 0; s < 4; ++s) {
            float acc = 0.f;
            #pragma unroll
            for (int k = 0; k < 8; ++k) {
                float f = xp[s * 8 + k];
                acc = fmaf(f, f, acc);
                xs[s][k] = f * (2.0f * L2E);
            }
            nsqx[s] = acc * (-L2E);
        }
    }
    __syncthreads();

    // DP state: mantissa e in [1,2), exponent q (int). Masked == q very negative.
    float e[2][4];
    int   q[2][4];
    #pragma unroll
    for (int s = 0; s < 4; ++s) {
        e[0][s] = 1.0f; e[1][s] = 1.0f;
        q[0][s] = BIGQ; q[1][s] = BIGQ;
    }

    // Y register pipeline: buffer (p)&3 holds row ja0(p) = p - 4*lane, as plain floats.
    float yp[4][8];
    float nyq[4];
    #pragma unroll
    for (int b = 0; b < 4; ++b) {
        nyq[b] = 0.f;
        #pragma unroll
        for (int k = 0; k < 8; ++k) yp[b][k] = 0.f;
    }

    const int lane4 = lane * 4;

    // prologue: buffer 0 <- row ja0(p=0) = -lane4 (wrapped; real only for lane 0)
    {
        unsigned jb = (unsigned)(-lane4) & 511u;
        int t   = (int)(jb >> 7) * 1152;
        int off = (int)((jb >> 2) & 31u);
        int A   = t + (int)(jb & 3u) * 256 + off * 4;
        float4 c0 = *reinterpret_cast<const float4*>(&sy[A]);
        float4 c1 = *reinterpret_cast<const float4*>(&sy[A + 128]);
        yp[0][0] = c0.x; yp[0][1] = c0.y; yp[0][2] = c0.z; yp[0][3] = c0.w;
        yp[0][4] = c1.x; yp[0][5] = c1.y; yp[0][6] = c1.z; yp[0][7] = c1.w;
        nyq[0] = sy[t + 1024 + (int)(jb & 3u) * 32 + off];
    }

    // shuffle pipeline: shC = shfl of slot3 from step p-1 (this step's s=0 "up"),
    //                   shP = shfl of slot3 from step p-2 (this step's s=0 "diag").
    float shCe = 1.0f, shPe = 1.0f;
    int   shCq = BIGQ, shPq = BIGQ;

    const int outA = a * 16 + b0;
    const bool storeLane = (lane == 31);

    // one DP cell: softmin(aligned add) * ex2(distance), exact exponent split
    #define CELL(S, BUF, EU, QU, EL, QL, ED, QD, WI)                                   \
    {                                                                                   \
        int qm = max(max((QU), (QL)), (QD));                                            \
        float sum = (scl_((EU), (QU) - qm) + scl_((EL), (QL) - qm))                     \
                  + scl_((ED), (QD) - qm);                                              \
        float acc = nsqx[S] + nyq[BUF];                                                 \
        _Pragma("unroll")                                                               \
        for (int k = 0; k < 8; ++k)                                                     \
            acc = fmaf(xs[S][k], yp[BUF][k], acc);                                      \
        float w = sum * ex2f_(acc);                                                     \
        unsigned wb = __float_as_uint(w);                                               \
        q[WI][S] = qm - 127 + (int)(wb >> 23);                                          \
        e[WI][S] = __uint_as_float((wb & 0x007FFFFFu) | 0x3F800000u);                   \
    }

    for (int p0 = 0; p0 < 640; p0 += 4) {
        const int j0      = p0 - lane4;
        const unsigned jc = (unsigned)j0 & 511u;
        const unsigned jn = (unsigned)(j0 + 4) & 511u;
        const int tOff0   = (int)(jc >> 7) * 1152;
        const int m0      = (int)((jc >> 2) & 31u);
        const int baseY0  = tOff0 + m0 * 4;
        const int qb0     = tOff0 + 1024 + m0;
        const int tOff1   = (int)(jn >> 7) * 1152;
        const int m1      = (int)((jn >> 2) & 31u);
        const int baseY1  = tOff1 + m1 * 4;
        const int qb1     = tOff1 + 1024 + m1;
        const bool bj0    = ((jc & 127u) == 0u);   // per-pair j==0 boundary: fires only at s==u
        const bool harv   = ((p0 & 127) == 124) && (p0 >= 252) && storeLane;
        const int  hIdx   = outA + ((p0 - 252) >> 7);

        #pragma unroll
        for (int u = 0; u < 4; ++u) {
            const int wIdx = u & 1;
            const int rIdx = wIdx ^ 1;

            // ---- slot 3 FIRST (reads prev2 q[wIdx][2] before slot 2 overwrites it) ----
            {
                float el = e[rIdx][3], ed = e[wIdx][2];
                int   ql, qd;
                if (u == 3) { ql = bj0 ? BIGQ : q[rIdx][3];  qd = bj0 ? BIGQ : q[wIdx][2]; }
                else        { ql = q[rIdx][3];               qd = q[wIdx][2]; }
                CELL(3, (u + 1) & 3, e[rIdx][2], q[rIdx][2], el, ql, ed, qd, wIdx)
            }

            // ---- shuffle slot3 for NEXT step, issued ~100 instr before its consumer ----
            const float shNe = __shfl_up_sync(0xffffffffu, e[wIdx][3], 1);
            const int   shNq = __shfl_up_sync(0xffffffffu, q[wIdx][3], 1);

            // ---- refill buffer (u+1)&3 (slot 3, its only pending reader, is done) ----
            {
                const int A = (u < 3) ? (baseY0 + (u + 1) * 256) : baseY1;
                const int b = (u + 1) & 3;
                float4 c0 = *reinterpret_cast<const float4*>(&sy[A]);
                float4 c1 = *reinterpret_cast<const float4*>(&sy[A + 128]);
                yp[b][0] = c0.x; yp[b][1] = c0.y; yp[b][2] = c0.z; yp[b][3] = c0.w;
                yp[b][4] = c1.x; yp[b][5] = c1.y; yp[b][6] = c1.z; yp[b][7] = c1.w;
                nyq[b] = (u < 3) ? sy[qb0 + (u + 1) * 32] : sy[qb1];
            }

            // ---- slots 2, 1 ----
            #pragma unroll
            for (int s = 2; s >= 1; --s) {
                float el = e[rIdx][s], ed = e[wIdx][s - 1];
                int   ql, qd;
                if (s == u) { ql = bj0 ? BIGQ : q[rIdx][s];  qd = bj0 ? BIGQ : q[wIdx][s - 1]; }
                else        { ql = q[rIdx][s];               qd = q[wIdx][s - 1]; }
                CELL(s, (u - s) & 3, e[rIdx][s - 1], q[rIdx][s - 1], el, ql, ed, qd, wIdx)
            }

            // ---- slot 0 (consumes the shuffles issued LAST step: shC/shP) ----
            {
                float eu = shCe, el, ed;
                int   qu = (lane == 0) ? BIGQ : shCq, ql, qd;
                if (u == 0) {
                    el = e[rIdx][0];  ql = bj0 ? BIGQ : q[rIdx][0];
                    if (lane == 0) { ed = 1.0f;  qd = bj0 ? 0 : BIGQ; }   // corner seed of each pair
                    else           { ed = shPe;  qd = bj0 ? BIGQ : shPq; }
                } else {
                    el = e[rIdx][0];  ql = q[rIdx][0];
                    ed = shPe;        qd = (lane == 0) ? BIGQ : shPq;
                }
                CELL(0, u & 3, eu, qu, el, ql, ed, qd, wIdx)
            }

            // ---- branch-free harvest: value computed unconditionally (cheap, once
            // per 4-step block), store is a single guarded statement -> bare @P STG,
            // no BSSY/BSYNC divergence machinery.
            if (u == 2) {
                float res = -((float)q[0][3] + lg2f_(e[0][3])) * LN2;
                if (harv) out[hIdx] = res;
            }

            // rotate shuffle pipeline
            shPe = shCe;  shPq = shCq;
            shCe = shNe;  shCq = shNq;
        }
    }
    #undef CELL
}

extern "C" void kernel_launch(void* const* d_in, const int* in_sizes, int n_in,
                              void* d_out, int out_size)
{
    const float* X = (const float*)d_in[0];
    const float* Y = (const float*)d_in[1];
    if (n_in >= 2 && in_sizes[0] < in_sizes[1]) {
        const float* t = X; X = Y; Y = t;
    }
    float* out = (float*)d_out;

    // 128 blocks x 128 threads: block = 4 a-values x one b-quad; warp = 4 chained pairs.
    // <=1 block per SM -> exactly 1 warp per SMSP, uniform load.
    sdtw_kernel<<<128, 128>>>(X, Y, out);
}